// round 16
// baseline (speedup 1.0000x reference)
#include <cuda_runtime.h>
#include <cstdint>

// Problem constants
#define T_ALL   32
#define B_BINS  32
#define G_MAX   64
#define NSLOT   33                   // u64 slots per (tt,g): slot k lo->cell k-1, hi->cell k

#define TB      8                    // t-values per CTA
#define TBLKS   (T_ALL / TB)         // 4
#define CHUNKS  37                   // 4*37 = 148 CTAs = 1/SM, co-resident
#define NBLOCKS (TBLKS * CHUNKS)     // 148
#define MAIN_THREADS 1024
#define SLICE   256
#define NGROUPS (MAIN_THREADS / SLICE)   // 4 slice-groups per CTA

#define SM_SLOTS (TB * G_MAX * NSLOT)       // 16896 u64 slots
#define SMEM_BYTES (SM_SLOTS * 8)           // 132 KB -> 1 CTA/SM

// z = 200*(lin_b - h) = b*D - H,  H = 200h + 220,  D = 440/31
#define DH_STEP  7.0967742f          // D/2
#define FB_MUL   14.0909091f         // 200*31/440
#define FB_ADD5  16.2818182f         // (220+4.0)*31/440 + 0.5 (ceil bias folded)
#define MAGIC_F  12582912.0f         // 2^23 + 2^22
#define MAGIC_I  0x4B400000

// Per-CTA partial slot arrays (u64, mod-2^64 exact -> deterministic).
// Fully overwritten every launch -> graph-replay safe.
__device__ __align__(16) unsigned long long g_part[NBLOCKS][SM_SLOTS]; // 20 MB
__device__ unsigned int bar_a = 0;
__device__ unsigned int bar_b = 0;

static __device__ __forceinline__ float tanh_approx(float x) {
    float y;
    asm("tanh.approx.f32 %0, %1;" : "=f"(y) : "f"(x));
    return y;
}
static __device__ __forceinline__ int f2i_rn_magic(float x) {
    return __float_as_int(x + MAGIC_F) - MAGIC_I;
}

// Branchless per-(item,t) update: ONE u64 atomic.
// slot b_sat gets V = (65536-q)<<32 | q  (negated for edges):
//   lo -> transition mass q at cell b_sat-1
//   hi -> differential 65536-q at cell b_sat (slot32 hi = discard bucket)
// b_sat clamped to [1,32] so the lo half ALWAYS lands in a real cell
// (clamping to 0 dropped full item mass -> the R15 4.4e-2 bug).
// q is the unconditional sigmoid (tanh saturates naturally -> no window bias).
template <bool EDGE>
static __device__ __forceinline__ void ect_update(
    unsigned long long* slotg, int tt, float h)
{
    // b_sat = clamp(ceil((H+4)/D), 1, 32); ceil via magic round (+0.5 folded)
    float fb = fmaf(h, FB_MUL, FB_ADD5);
    fb = fminf(fmaxf(fb, 1.1f), 32.4f);
    const float tmag  = fb + MAGIC_F;
    const int   b_sat = __float_as_int(tmag) - MAGIC_I;   // [1,32]
    const float blof  = tmag - MAGIC_F;                   // (float)b_sat
    // z/2 at transition bin b_sat-1 (true h, not clamped)
    const float zh = fmaf(blof, DH_STEP, fmaf(h, -100.0f, -110.0f - DH_STEP));

    const int q = f2i_rn_magic(fmaf(tanh_approx(zh), 32768.0f, 32768.0f));
    unsigned long long V =
        ((unsigned long long)(unsigned)(65536 - q) << 32) | (unsigned)q;
    if (EDGE) V = 0ull - V;
    atomicAdd(slotg + tt * (G_MAX * NSLOT) + b_sat, V);
}

// ---------------------------------------------------------------------------
// Fused persistent kernel (champion structure + fused u64 slot atomics).
// Phase 1: node/edge loops over 256-item interleaved slices; one ATOMS.64 per
//          (item,t); flush slots to per-CTA slab via STG.128.
// Grid barrier (148 co-resident CTAs). Phase 2: warp per (g,t): u64-sum 37
// chunk slots, exact (H,L) decomposition, neighbor-shfl, warp-scan, emit.
// ---------------------------------------------------------------------------
__global__ void __launch_bounds__(MAIN_THREADS, 1)
ect_fused_kernel(const float* __restrict__ x, const float* __restrict__ v,
                 const int* __restrict__ ei, const int* __restrict__ batch,
                 int N, int E, float* __restrict__ out)
{
    extern __shared__ unsigned long long s_slot[];

    const int tblk  = blockIdx.x / CHUNKS;
    const int chunk = blockIdx.x - tblk * CHUNKS;
    const int t0    = tblk * TB;
    const int tid   = threadIdx.x;
    const int gq    = tid >> 8;          // slice-group 0..3
    const int r     = tid & (SLICE - 1); // rank within slice

    {   // vectorized zero: 16896 u64 = 8448 uint4
        uint4* s4 = reinterpret_cast<uint4*>(s_slot);
        for (int i = tid; i < SM_SLOTS / 2; i += MAIN_THREADS)
            s4[i] = make_uint4(0u, 0u, 0u, 0u);
    }

    float v0[TB], v1[TB], v2[TB];
#pragma unroll
    for (int tt = 0; tt < TB; ++tt) {
        v0[tt] = __ldg(&v[0 * T_ALL + t0 + tt]);
        v1[tt] = __ldg(&v[1 * T_ALL + t0 + tt]);
        v2[tt] = __ldg(&v[2 * T_ALL + t0 + tt]);
    }
    __syncthreads();

    // ---- Node loop: 256-item slices, interleaved (<=1 slice imbalance).
    for (int s = chunk + CHUNKS * gq; s * SLICE < N; s += CHUNKS * NGROUPS) {
        const int i = s * SLICE + r;
        if (i >= N) continue;
        const float a0 = __ldg(&x[3 * i]);
        const float a1 = __ldg(&x[3 * i + 1]);
        const float a2 = __ldg(&x[3 * i + 2]);
        unsigned long long* slotg = s_slot + __ldg(&batch[i]) * NSLOT;
#pragma unroll
        for (int tt = 0; tt < TB; ++tt) {
            const float h = fmaf(a2, v2[tt], fmaf(a1, v1[tt], a0 * v0[tt]));
            ect_update<false>(slotg, tt, h);
        }
    }

    // ---- Edge loop
    for (int s = chunk + CHUNKS * gq; s * SLICE < E; s += CHUNKS * NGROUPS) {
        const int e = s * SLICE + r;
        if (e >= E) continue;
        const int sn = __ldg(&ei[e]);
        const int dn = __ldg(&ei[E + e]);
        const float a0 = __ldg(&x[3 * sn]);
        const float a1 = __ldg(&x[3 * sn + 1]);
        const float a2 = __ldg(&x[3 * sn + 2]);
        const float c0 = __ldg(&x[3 * dn]);
        const float c1 = __ldg(&x[3 * dn + 1]);
        const float c2 = __ldg(&x[3 * dn + 2]);
        unsigned long long* slotg = s_slot + __ldg(&batch[sn]) * NSLOT;
#pragma unroll
        for (int tt = 0; tt < TB; ++tt) {
            const float h1 = fmaf(a2, v2[tt], fmaf(a1, v1[tt], a0 * v0[tt]));
            const float h2 = fmaf(c2, v2[tt], fmaf(c1, v1[tt], c0 * v0[tt]));
            ect_update<true>(slotg, tt, fmaxf(h1, h2));
        }
    }

    __syncthreads();

    // Flush: vectorized stores to this CTA's private slab.
    {
        uint4* dst = reinterpret_cast<uint4*>(g_part[blockIdx.x]);
        const uint4* s4 = reinterpret_cast<const uint4*>(s_slot);
        for (int i = tid; i < SM_SLOTS / 2; i += MAIN_THREADS)
            dst[i] = s4[i];
    }
    __syncthreads();

    // ---- grid-wide barrier (148 co-resident CTAs) ----
    if (tid == 0) {
        unsigned int old;
        asm volatile("atom.add.release.gpu.u32 %0, [%1], %2;"
                     : "=r"(old) : "l"(&bar_a), "r"(1u) : "memory");
        unsigned int seen;
        do {
            asm volatile("ld.acquire.gpu.u32 %0, [%1];"
                         : "=r"(seen) : "l"(&bar_a) : "memory");
            if (seen >= (unsigned)NBLOCKS) break;
            __nanosleep(32);
        } while (true);
    }
    __syncthreads();

    // ---- Phase 2: warp per (g,t). lane = b = slot index (lane31 also slot 32).
    const int lane = tid & 31;
    const int gw   = blockIdx.x * (MAIN_THREADS / 32) + (tid >> 5);
    if (gw < G_MAX * T_ALL) {
        const int g     = gw >> 5;
        const int t     = gw & 31;
        const int ptblk = t / TB;
        const int ptt   = t % TB;
        const int off   = ptt * (G_MAX * NSLOT) + g * NSLOT + lane;

        unsigned long long Tm = 0ull, Tx = 0ull;
#pragma unroll 4
        for (int c = 0; c < CHUNKS; ++c) {
            const unsigned long long* slab = g_part[ptblk * CHUNKS + c];
            Tm += __ldcg(&slab[off]);
            if (lane == 31) Tx += __ldcg(&slab[off + 1]);   // slot 32
        }
        // Exact decomposition: T = H*2^32 + L with L = signed low word
        // (valid because |sum lo| and |sum hi| < 2^31).
        const int       L  = (int)(unsigned)Tm;
        const long long H  = ((long long)Tm - (long long)L) >> 32;
        const int       Lx = (int)(unsigned)Tx;
        int Lnext = __shfl_down_sync(0xFFFFFFFFu, L, 1);
        if (lane == 31) Lnext = Lx;
        int s = (int)H + Lnext;     // differential of cell b = lane

#pragma unroll
        for (int o = 1; o < 32; o <<= 1) {
            const int nb = __shfl_up_sync(0xFFFFFFFFu, s, o);
            if (lane >= o) s += nb;
        }
        out[g * (B_BINS * T_ALL) + lane * T_ALL + t] = (float)s * (1.0f / 65536.0f);
    }

    // ---- reset barrier counters for graph replay ----
    __syncthreads();
    if (tid == 0) {
        const unsigned int old = atomicAdd(&bar_b, 1u);
        if (old == (unsigned)(NBLOCKS - 1)) {
            bar_a = 0u;
            bar_b = 0u;
        }
    }
}

// ---------------------------------------------------------------------------
extern "C" void kernel_launch(void* const* d_in, const int* in_sizes, int n_in,
                              void* d_out, int out_size)
{
    const float* x     = (const float*)d_in[0];
    const float* v     = (const float*)d_in[1];
    const int*   ei    = (const int*)d_in[3];
    const int*   batch = (const int*)d_in[4];

    const int N = in_sizes[4];
    const int E = in_sizes[3] / 2;

    cudaFuncSetAttribute(ect_fused_kernel,
                         cudaFuncAttributeMaxDynamicSharedMemorySize, SMEM_BYTES);

    ect_fused_kernel<<<NBLOCKS, MAIN_THREADS, SMEM_BYTES>>>(
        x, v, ei, batch, N, E, (float*)d_out);
}

// round 17
// speedup vs baseline: 1.8889x; 1.8889x over previous
#include <cuda_runtime.h>
#include <cstdint>

// Problem constants
#define T_ALL   32
#define B_BINS  32
#define G_MAX   64
#define NSLOT   33                   // u32 slots per (tt,g): slot k lo16->cell k-1, hi16->cell k

#define TB      8                    // t-values per CTA
#define TBLKS   (T_ALL / TB)         // 4
#define CHUNKS  37                   // 4*37 = 148 CTAs = 1/SM, co-resident
#define NBLOCKS (TBLKS * CHUNKS)     // 148
#define MAIN_THREADS 1024
#define SLICE   128                  // <=1 slice of any graph per chunk -> field bound
#define NGROUPS (MAIN_THREADS / SLICE)   // 8 slice-groups per CTA

#define SM_SLOTS (TB * G_MAX * NSLOT)       // 16896 u32 slots
#define SMEM_BYTES (SM_SLOTS * 4)           // 66 KB

// z = 200*(lin_b - h) = b*D - H,  H = 200h + 220,  D = 440/31
#define DH_STEP  7.0967742f          // D/2
#define FB_MUL   14.0909091f         // 200*31/440
#define FB_ADD5  16.2818182f         // (220+4.0)*31/440 + 0.5 (ceil bias folded)
#define MAGIC_F  12582912.0f         // 2^23 + 2^22
#define MAGIC_I  0x4B400000

// Per-CTA partial slot arrays (u32 Q8 packed fields; mod-2^32 exact).
// Fully overwritten every launch -> graph-replay safe.
__device__ __align__(16) unsigned int g_part[NBLOCKS][SM_SLOTS];  // 10 MB
__device__ unsigned int bar_a = 0;
__device__ unsigned int bar_b = 0;

static __device__ __forceinline__ float tanh_approx(float x) {
    float y;
    asm("tanh.approx.f32 %0, %1;" : "=f"(y) : "f"(x));
    return y;
}
static __device__ __forceinline__ int f2i_rn_magic(float x) {
    return __float_as_int(x + MAGIC_F) - MAGIC_I;
}

// Branchless per-(item,t) update: ONE u32 atomic (Q8 packed).
// slot b_sat += (256-q)<<16 | q   (negated for edges, 2's complement):
//   lo16 -> transition mass q at cell b_sat-1
//   hi16 -> differential 256-q at cell b_sat (slot32 hi = discard bucket)
// b_sat clamped to [1,32] (R16 lesson: clamping to 0 drops item mass).
// q = round(sigmoid*256), unconditional (tanh saturates naturally).
template <bool EDGE>
static __device__ __forceinline__ void ect_update(
    unsigned int* slotg, int tt, float h)
{
    // b_sat = clamp(ceil((H+4)/D), 1, 32); ceil via magic round (+0.5 folded)
    float fb = fmaf(h, FB_MUL, FB_ADD5);
    fb = fminf(fmaxf(fb, 1.1f), 32.4f);
    const float tmag  = fb + MAGIC_F;
    const int   b_sat = __float_as_int(tmag) - MAGIC_I;   // [1,32]
    const float blof  = tmag - MAGIC_F;                   // (float)b_sat
    // z/2 at transition bin b_sat-1 (true h, not clamped)
    const float zh = fmaf(blof, DH_STEP, fmaf(h, -100.0f, -110.0f - DH_STEP));

    const int q = f2i_rn_magic(fmaf(tanh_approx(zh), 128.0f, 128.0f)); // [0,256]
    unsigned int V = ((unsigned int)(256 - q) << 16) | (unsigned int)q;
    if (EDGE) V = 0u - V;
    atomicAdd(slotg + tt * (G_MAX * NSLOT) + b_sat, V);
}

// ---------------------------------------------------------------------------
// Fused persistent kernel (champion structure + fused u32 Q8 slot atomics).
// Phase 1: node/edge loops over 128-item interleaved slices; one ATOMS.32 per
//          (item,t); flush slots to per-CTA slab via STG.128.
// Grid barrier (148 co-resident CTAs). Phase 2: warp per (g,t): per-chunk
// exact (H,L) field decomposition, sum, neighbor-shfl, warp-scan, emit.
// ---------------------------------------------------------------------------
__global__ void __launch_bounds__(MAIN_THREADS, 1)
ect_fused_kernel(const float* __restrict__ x, const float* __restrict__ v,
                 const int* __restrict__ ei, const int* __restrict__ batch,
                 int N, int E, float* __restrict__ out)
{
    extern __shared__ unsigned int s_slot[];

    const int tblk  = blockIdx.x / CHUNKS;
    const int chunk = blockIdx.x - tblk * CHUNKS;
    const int t0    = tblk * TB;
    const int tid   = threadIdx.x;
    const int gq    = tid / SLICE;       // slice-group 0..7
    const int r     = tid & (SLICE - 1); // rank within slice

    {   // vectorized zero: 16896 u32 = 4224 uint4
        uint4* s4 = reinterpret_cast<uint4*>(s_slot);
        for (int i = tid; i < SM_SLOTS / 4; i += MAIN_THREADS)
            s4[i] = make_uint4(0u, 0u, 0u, 0u);
    }

    float v0[TB], v1[TB], v2[TB];
#pragma unroll
    for (int tt = 0; tt < TB; ++tt) {
        v0[tt] = __ldg(&v[0 * T_ALL + t0 + tt]);
        v1[tt] = __ldg(&v[1 * T_ALL + t0 + tt]);
        v2[tt] = __ldg(&v[2 * T_ALL + t0 + tt]);
    }
    __syncthreads();

    // ---- Node loop: 128-item slices, interleaved (<=1 slice imbalance,
    //      and <=1 slice of any single graph per chunk -> field bounds).
    for (int s = chunk + CHUNKS * gq; s * SLICE < N; s += CHUNKS * NGROUPS) {
        const int i = s * SLICE + r;
        if (i >= N) continue;
        const float a0 = __ldg(&x[3 * i]);
        const float a1 = __ldg(&x[3 * i + 1]);
        const float a2 = __ldg(&x[3 * i + 2]);
        unsigned int* slotg = s_slot + __ldg(&batch[i]) * NSLOT;
#pragma unroll
        for (int tt = 0; tt < TB; ++tt) {
            const float h = fmaf(a2, v2[tt], fmaf(a1, v1[tt], a0 * v0[tt]));
            ect_update<false>(slotg, tt, h);
        }
    }

    // ---- Edge loop
    for (int s = chunk + CHUNKS * gq; s * SLICE < E; s += CHUNKS * NGROUPS) {
        const int e = s * SLICE + r;
        if (e >= E) continue;
        const int sn = __ldg(&ei[e]);
        const int dn = __ldg(&ei[E + e]);
        const float a0 = __ldg(&x[3 * sn]);
        const float a1 = __ldg(&x[3 * sn + 1]);
        const float a2 = __ldg(&x[3 * sn + 2]);
        const float c0 = __ldg(&x[3 * dn]);
        const float c1 = __ldg(&x[3 * dn + 1]);
        const float c2 = __ldg(&x[3 * dn + 2]);
        unsigned int* slotg = s_slot + __ldg(&batch[sn]) * NSLOT;
#pragma unroll
        for (int tt = 0; tt < TB; ++tt) {
            const float h1 = fmaf(a2, v2[tt], fmaf(a1, v1[tt], a0 * v0[tt]));
            const float h2 = fmaf(c2, v2[tt], fmaf(c1, v1[tt], c0 * v0[tt]));
            ect_update<true>(slotg, tt, fmaxf(h1, h2));
        }
    }

    __syncthreads();

    // Flush: vectorized stores to this CTA's private slab.
    {
        uint4* dst = reinterpret_cast<uint4*>(g_part[blockIdx.x]);
        const uint4* s4 = reinterpret_cast<const uint4*>(s_slot);
        for (int i = tid; i < SM_SLOTS / 4; i += MAIN_THREADS)
            dst[i] = s4[i];
    }
    __syncthreads();

    // ---- grid-wide barrier (148 co-resident CTAs) ----
    if (tid == 0) {
        unsigned int old;
        asm volatile("atom.add.release.gpu.u32 %0, [%1], %2;"
                     : "=r"(old) : "l"(&bar_a), "r"(1u) : "memory");
        unsigned int seen;
        do {
            asm volatile("ld.acquire.gpu.u32 %0, [%1];"
                         : "=r"(seen) : "l"(&bar_a) : "memory");
            if (seen >= (unsigned)NBLOCKS) break;
            __nanosleep(32);
        } while (true);
    }
    __syncthreads();

    // ---- Phase 2: warp per (g,t). lane = b = slot index (lane31 also slot 32).
    // Per-chunk exact decomposition T = H*2^16 + L (L = signed 16-bit low,
    // valid because per-chunk per-slot |field sums| < 2^15), then integer sums.
    const int lane = tid & 31;
    const int gw   = blockIdx.x * (MAIN_THREADS / 32) + (tid >> 5);
    if (gw < G_MAX * T_ALL) {
        const int g     = gw >> 5;
        const int t     = gw & 31;
        const int ptblk = t / TB;
        const int ptt   = t % TB;
        const int off   = ptt * (G_MAX * NSLOT) + g * NSLOT + lane;

        int sumL = 0, sumH = 0, sumLx = 0;
#pragma unroll 4
        for (int c = 0; c < CHUNKS; ++c) {
            const unsigned int* slab = g_part[ptblk * CHUNKS + c];
            const unsigned int Tm = __ldcg(&slab[off]);
            const int L = (int)(short)(Tm & 0xFFFFu);
            sumL += L;
            sumH += ((int)Tm - L) >> 16;
            if (lane == 31) {
                const unsigned int Tx = __ldcg(&slab[off + 1]);   // slot 32
                sumLx += (int)(short)(Tx & 0xFFFFu);
            }
        }
        int Lnext = __shfl_down_sync(0xFFFFFFFFu, sumL, 1);
        if (lane == 31) Lnext = sumLx;
        int s = sumH + Lnext;        // differential of cell b = lane (Q8)

#pragma unroll
        for (int o = 1; o < 32; o <<= 1) {
            const int nb = __shfl_up_sync(0xFFFFFFFFu, s, o);
            if (lane >= o) s += nb;
        }
        out[g * (B_BINS * T_ALL) + lane * T_ALL + t] = (float)s * (1.0f / 256.0f);
    }

    // ---- reset barrier counters for graph replay ----
    __syncthreads();
    if (tid == 0) {
        const unsigned int old = atomicAdd(&bar_b, 1u);
        if (old == (unsigned)(NBLOCKS - 1)) {
            bar_a = 0u;
            bar_b = 0u;
        }
    }
}

// ---------------------------------------------------------------------------
extern "C" void kernel_launch(void* const* d_in, const int* in_sizes, int n_in,
                              void* d_out, int out_size)
{
    const float* x     = (const float*)d_in[0];
    const float* v     = (const float*)d_in[1];
    const int*   ei    = (const int*)d_in[3];
    const int*   batch = (const int*)d_in[4];

    const int N = in_sizes[4];
    const int E = in_sizes[3] / 2;

    cudaFuncSetAttribute(ect_fused_kernel,
                         cudaFuncAttributeMaxDynamicSharedMemorySize, SMEM_BYTES);

    ect_fused_kernel<<<NBLOCKS, MAIN_THREADS, SMEM_BYTES>>>(
        x, v, ei, batch, N, E, (float*)d_out);
}